// round 10
// baseline (speedup 1.0000x reference)
#include <cuda_runtime.h>
#include <cuda_bf16.h>
#include <cuda_fp16.h>
#include <cuda_fp8.h>
#include <cstdint>

#define BB   2
#define CC   128
#define HH   48
#define NTOK 2304
#define NHEADS 8
#define CHH  16
#define KTOP 1843

typedef unsigned long long ull;

// ---------------- scratch ----------------
__device__ __nv_bfloat16 g_q16[BB*CC*NTOK];          // raw q bf16, [b*C+c][n]
__device__ __nv_bfloat16 g_kT[BB*NHEADS*NTOK*CHH];   // NORMALIZED K, [bh][n][ch-pair-permuted]
__device__ unsigned char g_v8[BB*CC*NTOK];           // v e4m3 (scaled), token-pair-permuted
__device__ float g_vsinv[BB*CC];                     // per-channel V inverse scale
__device__ float g_attn[BB*CC*NTOK];

// ---------------- fp8 helpers ----------------
__device__ __forceinline__ unsigned short pack2_e4m3(float lo, float hi) {
    unsigned short r;
    asm("cvt.rn.satfinite.e4m3x2.f32 %0, %1, %2;" : "=h"(r) : "f"(hi), "f"(lo));
    return r;
}
__device__ __forceinline__ unsigned f2e4m3(float f) {
    return (unsigned)__nv_cvt_float_to_fp8(f, __NV_SATFINITE, __NV_E4M3);
}
// monotone byte keymap over 4 packed e4m3 (forward)
__device__ __forceinline__ unsigned keymap4(unsigned u) {
    unsigned m = u & 0x80808080u;
    unsigned X = 0x80808080u | ((m >> 7) * 0x7Fu);
    return u ^ X;
}
// pair-permute slot map: u32 j (0..7) -> slot (pairs (j, j+4) adjacent)
__device__ __forceinline__ int sperm(int j) { return (j < 4) ? 2*j : 2*j - 7; }

// ---------------- mma wrappers ----------------
__device__ __forceinline__ void mma_bf16(float& c0, float& c1, float& c2, float& c3,
                                         unsigned a0, unsigned a1, unsigned a2, unsigned a3,
                                         unsigned b0, unsigned b1) {
    asm volatile("mma.sync.aligned.m16n8k16.row.col.f32.bf16.bf16.f32 "
                 "{%0,%1,%2,%3}, {%4,%5,%6,%7}, {%8,%9}, {%0,%1,%2,%3};"
                 : "+f"(c0), "+f"(c1), "+f"(c2), "+f"(c3)
                 : "r"(a0), "r"(a1), "r"(a2), "r"(a3), "r"(b0), "r"(b1));
}
__device__ __forceinline__ void mma_e4m3(float& c0, float& c1, float& c2, float& c3,
                                         unsigned a0, unsigned a1, unsigned a2, unsigned a3,
                                         unsigned b0, unsigned b1) {
    asm volatile("mma.sync.aligned.m16n8k32.row.col.f32.e4m3.e4m3.f32 "
                 "{%0,%1,%2,%3}, {%4,%5,%6,%7}, {%8,%9}, {%0,%1,%2,%3};"
                 : "+f"(c0), "+f"(c1), "+f"(c2), "+f"(c3)
                 : "r"(a0), "r"(a1), "r"(a2), "r"(a3), "r"(b0), "r"(b1));
}

// =================================================================
// Kernel 1: qkv convs, 2 channels/block, 768 threads (3 px/thread),
// 2-channel-batched x loads, in-kernel epilogues.
// grid = (BB*64, 3): y 0=q, 1=k(norm), 2=v(fp8)
// =================================================================
__global__ __launch_bounds__(768) void qkv_kernel(
    const float* __restrict__ x,
    const float* __restrict__ wq, const float* __restrict__ wk, const float* __restrict__ wv,
    const float* __restrict__ dwq, const float* __restrict__ dwk, const float* __restrict__ dwv)
{
    __shared__ float sp[2][NTOK + 8];
    __shared__ float wp[2][32];
    __shared__ float wd[2][9];
    __shared__ float redw[2][24];
    __shared__ float s_sc[2];

    const int t  = blockIdx.y;
    const int b  = blockIdx.x >> 6;
    const int cp = blockIdx.x & 63;
    const int c0 = cp * 2;
    const int g  = c0 >> 5;
    const int tid = threadIdx.x;
    const int lane = tid & 31;

    const float* wsel = (t == 0) ? wq : (t == 1) ? wk : wv;
    const float* dsel = (t == 0) ? dwq : (t == 1) ? dwk : dwv;

    if (tid < 64) wp[tid >> 5][tid & 31] = wsel[(c0 + (tid >> 5))*32 + (tid & 31)];
    if (tid < 18) wd[tid / 9][tid % 9]   = dsel[(c0 + tid/9)*9 + tid % 9];
    __syncthreads();

    // pointwise grouped conv, 2 out-channels, 2 in-channels per step (MLP=6)
    const float* xb = x + (size_t)(b*CC + g*32) * NTOK + tid;
    float a0[3], a1[3];
#pragma unroll
    for (int p = 0; p < 3; ++p) { a0[p] = 0.f; a1[p] = 0.f; }
    for (int i = 0; i < 32; i += 2) {
        float x0[3], x1[3];
        const float* xi0 = xb + (size_t)i*NTOK;
        const float* xi1 = xb + (size_t)(i+1)*NTOK;
#pragma unroll
        for (int p = 0; p < 3; ++p) { x0[p] = xi0[p*768]; x1[p] = xi1[p*768]; }
        const float w00 = wp[0][i], w01 = wp[0][i+1];
        const float w10 = wp[1][i], w11 = wp[1][i+1];
#pragma unroll
        for (int p = 0; p < 3; ++p) {
            a0[p] += w00*x0[p] + w01*x1[p];
            a1[p] += w10*x0[p] + w11*x1[p];
        }
    }
#pragma unroll
    for (int p = 0; p < 3; ++p) { sp[0][tid + p*768] = a0[p]; sp[1][tid + p*768] = a1[p]; }
    __syncthreads();

    // depthwise 3x3 SAME + per-channel stat
    float d0[3], d1[3];
    float rv0 = 0.f, rv1 = 0.f;
#pragma unroll
    for (int p = 0; p < 3; ++p) {
        int n = tid + p*768;
        int r = n / HH;
        int col = n - r*HH;
        float s0 = 0.f, s1 = 0.f;
#pragma unroll
        for (int dy = 0; dy < 3; ++dy) {
            int rr = r + dy - 1;
            if ((unsigned)rr < (unsigned)HH) {
#pragma unroll
                for (int dx = 0; dx < 3; ++dx) {
                    int cc2 = col + dx - 1;
                    if ((unsigned)cc2 < (unsigned)HH) {
                        int nn = rr*HH + cc2;
                        int ki = dy*3 + dx;
                        s0 += wd[0][ki] * sp[0][nn];
                        s1 += wd[1][ki] * sp[1][nn];
                    }
                }
            }
        }
        d0[p] = s0; d1[p] = s1;
        if (t == 1)      { rv0 += s0*s0;                rv1 += s1*s1; }
        else if (t == 2) { rv0 = fmaxf(rv0, fabsf(s0)); rv1 = fmaxf(rv1, fabsf(s1)); }
    }

    float sc0 = 1.f, sc1 = 1.f;
    if (t != 0) {
#pragma unroll
        for (int off = 16; off; off >>= 1) {
            float o0 = __shfl_xor_sync(0xffffffffu, rv0, off);
            float o1 = __shfl_xor_sync(0xffffffffu, rv1, off);
            if (t == 1) { rv0 += o0; rv1 += o1; }
            else        { rv0 = fmaxf(rv0, o0); rv1 = fmaxf(rv1, o1); }
        }
        if (lane == 0) { redw[0][tid >> 5] = rv0; redw[1][tid >> 5] = rv1; }
        __syncthreads();
        if (tid < 32) {
            float v0 = (tid < 24) ? redw[0][tid] : 0.f;
            float v1 = (tid < 24) ? redw[1][tid] : 0.f;
#pragma unroll
            for (int off = 16; off; off >>= 1) {
                float o0 = __shfl_xor_sync(0xffffffffu, v0, off);
                float o1 = __shfl_xor_sync(0xffffffffu, v1, off);
                if (t == 1) { v0 += o0; v1 += o1; }
                else        { v0 = fmaxf(v0, o0); v1 = fmaxf(v1, o1); }
            }
            if (tid == 0) {
                if (t == 1) {
                    s_sc[0] = 1.f / fmaxf(sqrtf(v0), 1e-12f);
                    s_sc[1] = 1.f / fmaxf(sqrtf(v1), 1e-12f);
                } else {
                    s_sc[0] = (v0 > 0.f) ? 240.f / v0 : 0.f;
                    s_sc[1] = (v1 > 0.f) ? 240.f / v1 : 0.f;
                    g_vsinv[b*CC + c0]     = (v0 > 0.f) ? v0 / 240.f : 0.f;
                    g_vsinv[b*CC + c0 + 1] = (v1 > 0.f) ? v1 / 240.f : 0.f;
                }
            }
        }
        __syncthreads();
        sc0 = s_sc[0]; sc1 = s_sc[1];
    }

    if (t == 0) {
        __nv_bfloat16* q0 = g_q16 + (size_t)(b*CC + c0)*NTOK;
        __nv_bfloat16* q1 = g_q16 + (size_t)(b*CC + c0 + 1)*NTOK;
#pragma unroll
        for (int p = 0; p < 3; ++p) {
            int n = tid + p*768;
            q0[n] = __float2bfloat16(d0[p]);
            q1[n] = __float2bfloat16(d1[p]);
        }
    } else if (t == 1) {
        const int bh = b*NHEADS + (c0 >> 4);
        const int j  = (c0 & 15) >> 1;
        const int slot = sperm(j);
        __nv_bfloat16* kTp = g_kT + (size_t)bh*NTOK*CHH + slot*2;
#pragma unroll
        for (int p = 0; p < 3; ++p) {
            int n = tid + p*768;
            kTp[(size_t)n*16]     = __float2bfloat16(d0[p] * sc0);
            kTp[(size_t)n*16 + 1] = __float2bfloat16(d1[p] * sc1);
        }
    } else {
        unsigned char* v0 = g_v8 + (size_t)(b*CC + c0)*NTOK;
        unsigned char* v1 = g_v8 + (size_t)(b*CC + c0 + 1)*NTOK;
#pragma unroll
        for (int p = 0; p < 3; ++p) {
            int n = tid + p*768;
            int np = (n & ~31) | (sperm((n >> 2) & 7) * 4) | (n & 3);
            v0[np] = (unsigned char)f2e4m3(d0[p] * sc0);
            v1[np] = (unsigned char)f2e4m3(d1[p] * sc1);
        }
    }
}

// =================================================================
// Kernel 2: fused attention. 512 threads, 3 CTAs/SM (reg-trimmed).
// grid = (144, 16)
// =================================================================
#define SROWB 2320
#define ATTN_SM_S   (16*SROWB)
#define ATTN_SM_QA  512
#define ATTN_SM_SCR (16*256*4)
#define ATTN_SM_ZS  (16*16*4)
#define ATTN_SMEM_BYTES (ATTN_SM_S + ATTN_SM_QA + ATTN_SM_SCR + ATTN_SM_ZS)

__global__ __launch_bounds__(512, 3) void attn_kernel(const float* __restrict__ temperature)
{
    extern __shared__ unsigned char smraw[];
    unsigned char* smS = smraw;
    __nv_bfloat16* qA  = (__nv_bfloat16*)(smraw + ATTN_SM_S);
    float* scratch     = (float*)(smraw + ATTN_SM_S + ATTN_SM_QA);
    float* zs          = (float*)(smraw + ATTN_SM_S + ATTN_SM_QA + ATTN_SM_SCR);

    const int rt = blockIdx.x, bh = blockIdx.y;
    const int b = bh >> 3, h = bh & 7;
    const int bc0 = b*CC + h*CHH;
    const int row0 = rt * 16;
    const int tid = threadIdx.x;
    const int w = tid >> 5, lane = tid & 31;
    const float ts = temperature[h];

    // ---- phase 0: Q rows, L2-normalize over C_h, fold temperature ----
    if (tid < 256) {
        int r = tid >> 4, c = tid & 15;
        float qv = __bfloat162float(g_q16[(size_t)(bc0 + c)*NTOK + row0 + r]);
        float ss = qv * qv;
#pragma unroll
        for (int off = 8; off; off >>= 1) ss += __shfl_xor_sync(0xffffffffu, ss, off, 16);
        float qt = qv * ts / fmaxf(sqrtf(ss), 1e-12f);
        qA[r*16 + c] = __float2bfloat16(qt);
    }
    __syncthreads();

    // ---- phase 1: scores via bf16 mma -> keymapped e4m3 smem ----
    {
        const unsigned* qAu = (const unsigned*)qA;
        int r = lane >> 2, kx = (lane & 3) * 2;
        unsigned a0 = qAu[(r*16 + kx) >> 1];
        unsigned a1 = qAu[((r+8)*16 + kx) >> 1];
        unsigned a2 = qAu[(r*16 + kx + 8) >> 1];
        unsigned a3 = qAu[((r+8)*16 + kx + 8) >> 1];

        const ull* kT64 = (const ull*)(g_kT + (size_t)bh * NTOK * CHH);
        const int jl = lane >> 2, ko = lane & 3;
        const int cst = (lane & 3) * 2;
#pragma unroll
        for (int mb = 0; mb < 6; ++mb) {
            ull rbb[3];
#pragma unroll
            for (int m = 0; m < 3; ++m) {
                int j0 = w*144 + (mb*3 + m)*8;
                rbb[m] = kT64[(size_t)(j0 + jl)*4 + ko];
            }
#pragma unroll
            for (int m = 0; m < 3; ++m) {
                int j0 = w*144 + (mb*3 + m)*8;
                float c0 = 0.f, c1 = 0.f, c2 = 0.f, c3 = 0.f;
                mma_bf16(c0, c1, c2, c3, a0, a1, a2, a3,
                         (unsigned)rbb[m], (unsigned)(rbb[m] >> 32));
                int off = j0 + cst;
                unsigned comb = (unsigned)pack2_e4m3(c0, c1)
                              | ((unsigned)pack2_e4m3(c2, c3) << 16);
                comb = keymap4(comb);
                *(unsigned short*)(smS + r*SROWB + off)     = (unsigned short)comb;
                *(unsigned short*)(smS + (r+8)*SROWB + off) = (unsigned short)(comb >> 16);
            }
        }
    }
    __syncthreads();

    // ---- phase 2: half-row register cache + 4-pass binary search ----
    unsigned* srowU = (unsigned*)(smS + (size_t)w * SROWB);
    unsigned rr[9];
#pragma unroll
    for (int it = 0; it < 9; ++it) rr[it] = srowU[lane + it*32];

    int lo = 0, hi = 15;
#pragma unroll
    for (int pass = 0; pass < 4; ++pass) {
        int mid = (lo + hi + 1) >> 1;
        unsigned t4 = (unsigned)(mid << 4) * 0x01010101u;
        int cnt = 0;
#pragma unroll
        for (int it = 0; it < 9; ++it)
            cnt = __dp4a((int)__vsetgeu4(rr[it], t4), 0x01010101, cnt);
#pragma unroll
        for (int it = 9; it < 18; ++it)
            cnt = __dp4a((int)__vsetgeu4(srowU[lane + it*32], t4), 0x01010101, cnt);
#pragma unroll
        for (int off = 16; off; off >>= 1) cnt += __shfl_xor_sync(0xffffffffu, cnt, off);
        if (cnt >= KTOP) lo = mid; else hi = mid - 1;
    }
    const unsigned tk4 = ((unsigned)(lo << 4)) * 0x01010101u;

    // ---- phase 3: masked f16x2 softmax weights (shift by |ts|), in place ----
    {
        const float l2ef = 1.4426950408889634f;
        const float shift = fabsf(ts);
        const __half2 hl2e = __float2half2_rn(l2ef);
        const __half2 hb   = __float2half2_rn(-shift * l2ef);
#pragma unroll
        for (int it = 0; it < 18; ++it) {
            unsigned k = (it < 9) ? rr[it] : srowU[lane + it*32];
            unsigned mff = __vcmpgeu4(k, tk4);
            unsigned sb = (k & 0x80808080u) >> 7;
            unsigned u = (~k) ^ (sb * 0x7Fu);
            unsigned hlo, hhi;
            asm("cvt.rn.f16x2.e4m3x2 %0, %1;" : "=r"(hlo) : "h"((unsigned short)(u & 0xffffu)));
            asm("cvt.rn.f16x2.e4m3x2 %0, %1;" : "=r"(hhi) : "h"((unsigned short)(u >> 16)));
            __half2 alo = __hfma2(*(__half2*)&hlo, hl2e, hb);
            __half2 ahi = __hfma2(*(__half2*)&hhi, hl2e, hb);
            unsigned wlo, whi;
            asm("ex2.approx.f16x2 %0, %1;" : "=r"(wlo) : "r"(*(unsigned*)&alo));
            asm("ex2.approx.f16x2 %0, %1;" : "=r"(whi) : "r"(*(unsigned*)&ahi));
            unsigned short plo, phi;
            asm("cvt.rn.satfinite.e4m3x2.f16x2 %0, %1;" : "=h"(plo) : "r"(wlo));
            asm("cvt.rn.satfinite.e4m3x2.f16x2 %0, %1;" : "=h"(phi) : "r"(whi));
            srowU[lane + it*32] = ((unsigned)plo | ((unsigned)phi << 16)) & mff;
        }
    }
    __syncthreads();

    // ---- phase 4: PV via fp8 mma (LDG.64 V) + ones-column mma for Z ----
    float acc[8];
#pragma unroll
    for (int i = 0; i < 8; ++i) acc[i] = 0.f;
    float za0 = 0.f, za1 = 0.f, za2 = 0.f, za3 = 0.f;
    {
        const unsigned char* vb = g_v8 + (size_t)bc0 * NTOK;
        const int r = lane >> 2, ko = lane & 3, kx = ko * 4;
        const int nn = lane >> 2;
        const unsigned bz = (lane < 4) ? 0x38383838u : 0u;   // e4m3 1.0 in col 0
        for (int k0 = w*32; k0 < NTOK; k0 += 512) {
            unsigned A0 = *(const unsigned*)(smS + r*SROWB + k0 + kx);
            unsigned A1 = *(const unsigned*)(smS + (r+8)*SROWB + k0 + kx);
            unsigned A2 = *(const unsigned*)(smS + r*SROWB + k0 + kx + 16);
            unsigned A3 = *(const unsigned*)(smS + (r+8)*SROWB + k0 + kx + 16);
            ull bb01 = *(const ull*)(vb + (size_t)nn*NTOK + k0 + 8*ko);
            ull bb23 = *(const ull*)(vb + (size_t)(nn+8)*NTOK + k0 + 8*ko);
            mma_e4m3(acc[0], acc[1], acc[2], acc[3], A0, A1, A2, A3,
                     (unsigned)bb01, (unsigned)(bb01 >> 32));
            mma_e4m3(acc[4], acc[5], acc[6], acc[7], A0, A1, A2, A3,
                     (unsigned)bb23, (unsigned)(bb23 >> 32));
            mma_e4m3(za0, za1, za2, za3, A0, A1, A2, A3, bz, bz);
        }
    }
    {
        int r = lane >> 2, c2s = (lane & 3) * 2;
        float* sw = scratch + w*256;
        sw[r*16 + c2s]           = acc[0];
        sw[r*16 + c2s + 1]       = acc[1];
        sw[(r+8)*16 + c2s]       = acc[2];
        sw[(r+8)*16 + c2s + 1]   = acc[3];
        sw[r*16 + 8 + c2s]       = acc[4];
        sw[r*16 + 8 + c2s + 1]   = acc[5];
        sw[(r+8)*16 + 8 + c2s]   = acc[6];
        sw[(r+8)*16 + 8 + c2s+1] = acc[7];
        if ((lane & 3) == 0) {
            zs[w*16 + r]     = za0;
            zs[w*16 + 8 + r] = za2;
        }
    }
    __syncthreads();

    // ---- phase 5: cross-warp reduce, z-normalize, unscale, write ----
    if (tid < 256) {
        int r = tid >> 4, c = tid & 15;
        float s = 0.f, zr = 0.f;
#pragma unroll
        for (int wi = 0; wi < 16; ++wi) {
            s  += scratch[wi*256 + r*16 + c];
            zr += zs[wi*16 + r];
        }
        g_attn[(size_t)(bc0 + c)*NTOK + row0 + r] = s / zr * g_vsinv[bc0 + c];
    }
}

// =================================================================
// Kernel 3: out = x + wo @ attn via bf16 tensor cores.
// grid = (72, 2), 256 threads (8 warps; warp = 16 c_out rows)
// =================================================================
#define OC_STRIDE 136
#define OC_SMEM_BYTES ((128*OC_STRIDE + 32*OC_STRIDE) * 2)

__global__ __launch_bounds__(256) void outconv_kernel(
    const float* __restrict__ x, const float* __restrict__ wo, float* __restrict__ out)
{
    extern __shared__ __nv_bfloat16 smoc[];
    __nv_bfloat16* wos = smoc;                      // [128][136]
    __nv_bfloat16* ats = smoc + 128*OC_STRIDE;      // [32 tokens][136 channels]

    const int b  = blockIdx.y;
    const int n0 = blockIdx.x * 32;
    const int tid = threadIdx.x;

    for (int l = tid; l < 16384; l += 256)
        wos[(l >> 7)*OC_STRIDE + (l & 127)] = __float2bfloat16(wo[l]);
    for (int l = tid; l < 4096; l += 256) {
        int c = l >> 5, nl = l & 31;
        ats[nl*OC_STRIDE + c] = __float2bfloat16(g_attn[(size_t)(b*CC + c)*NTOK + n0 + nl]);
    }
    __syncthreads();

    const int w = tid >> 5, lane = tid & 31;
    const int r = lane >> 2, kq = (lane & 3) * 2;

    float acc[4][4];
#pragma unroll
    for (int ng = 0; ng < 4; ++ng)
#pragma unroll
        for (int i = 0; i < 4; ++i) acc[ng][i] = 0.f;

#pragma unroll
    for (int kc = 0; kc < 8; ++kc) {
        const int k0 = kc * 16;
        unsigned a0 = *(const unsigned*)&wos[(w*16 + r)*OC_STRIDE + k0 + kq];
        unsigned a1 = *(const unsigned*)&wos[(w*16 + r + 8)*OC_STRIDE + k0 + kq];
        unsigned a2 = *(const unsigned*)&wos[(w*16 + r)*OC_STRIDE + k0 + kq + 8];
        unsigned a3 = *(const unsigned*)&wos[(w*16 + r + 8)*OC_STRIDE + k0 + kq + 8];
#pragma unroll
        for (int ng = 0; ng < 4; ++ng) {
            unsigned b0 = *(const unsigned*)&ats[(ng*8 + r)*OC_STRIDE + k0 + kq];
            unsigned b1 = *(const unsigned*)&ats[(ng*8 + r)*OC_STRIDE + k0 + kq + 8];
            mma_bf16(acc[ng][0], acc[ng][1], acc[ng][2], acc[ng][3],
                     a0, a1, a2, a3, b0, b1);
        }
    }

#pragma unroll
    for (int ng = 0; ng < 4; ++ng) {
        const int col = n0 + ng*8 + kq;
        size_t i0 = (size_t)(b*CC + w*16 + r)*NTOK + col;
        float2 x0 = *(const float2*)(x + i0);
        *(float2*)(out + i0) = make_float2(x0.x + acc[ng][0], x0.y + acc[ng][1]);
        size_t i1 = (size_t)(b*CC + w*16 + r + 8)*NTOK + col;
        float2 x1 = *(const float2*)(x + i1);
        *(float2*)(out + i1) = make_float2(x1.x + acc[ng][2], x1.y + acc[ng][3]);
    }
}

// =================================================================
extern "C" void kernel_launch(void* const* d_in, const int* in_sizes, int n_in,
                              void* d_out, int out_size)
{
    const float* x    = (const float*)d_in[0];
    const float* wq   = (const float*)d_in[1];
    const float* wk   = (const float*)d_in[2];
    const float* wv   = (const float*)d_in[3];
    const float* dwq  = (const float*)d_in[4];
    const float* dwk  = (const float*)d_in[5];
    const float* dwv  = (const float*)d_in[6];
    const float* wo   = (const float*)d_in[7];
    const float* temp = (const float*)d_in[8];
    float* out = (float*)d_out;

    cudaFuncSetAttribute(attn_kernel, cudaFuncAttributeMaxDynamicSharedMemorySize, ATTN_SMEM_BYTES);
    cudaFuncSetAttribute(outconv_kernel, cudaFuncAttributeMaxDynamicSharedMemorySize, OC_SMEM_BYTES);

    qkv_kernel<<<dim3(BB*64, 3), 768>>>(x, wq, wk, wv, dwq, dwk, dwv);
    attn_kernel<<<dim3(NTOK/16, BB*NHEADS), 512, ATTN_SMEM_BYTES>>>(temp);
    outconv_kernel<<<dim3(NTOK/32, BB), 256, OC_SMEM_BYTES>>>(x, wo, out);
}

// round 11
// speedup vs baseline: 1.0416x; 1.0416x over previous
#include <cuda_runtime.h>
#include <cuda_bf16.h>
#include <cuda_fp16.h>
#include <cuda_fp8.h>
#include <cstdint>

#define BB   2
#define CC   128
#define HH   48
#define NTOK 2304
#define NHEADS 8
#define CHH  16
#define KTOP 1843

typedef unsigned long long ull;

// ---------------- scratch ----------------
__device__ __nv_bfloat16 g_q16[BB*CC*NTOK];          // raw q bf16, [b*C+c][n]
__device__ __nv_bfloat16 g_kT[BB*NHEADS*NTOK*CHH];   // NORMALIZED K, [bh][n][ch-pair-permuted]
__device__ unsigned char g_v8[BB*CC*NTOK];           // v e4m3 (scaled), token-pair-permuted
__device__ float g_vsinv[BB*CC];                     // per-channel V inverse scale
__device__ float g_attn[BB*CC*NTOK];

// ---------------- fp8 helpers ----------------
__device__ __forceinline__ unsigned short pack2_e4m3(float lo, float hi) {
    unsigned short r;
    asm("cvt.rn.satfinite.e4m3x2.f32 %0, %1, %2;" : "=h"(r) : "f"(hi), "f"(lo));
    return r;
}
__device__ __forceinline__ unsigned f2e4m3(float f) {
    return (unsigned)__nv_cvt_float_to_fp8(f, __NV_SATFINITE, __NV_E4M3);
}
// monotone byte keymap over 4 packed e4m3 (forward)
__device__ __forceinline__ unsigned keymap4(unsigned u) {
    unsigned m = u & 0x80808080u;
    unsigned X = 0x80808080u | ((m >> 7) * 0x7Fu);
    return u ^ X;
}
// pair-permute slot map: u32 j (0..7) -> slot (pairs (j, j+4) adjacent)
__device__ __forceinline__ int sperm(int j) { return (j < 4) ? 2*j : 2*j - 7; }

// ---------------- mma wrappers ----------------
__device__ __forceinline__ void mma_bf16(float& c0, float& c1, float& c2, float& c3,
                                         unsigned a0, unsigned a1, unsigned a2, unsigned a3,
                                         unsigned b0, unsigned b1) {
    asm volatile("mma.sync.aligned.m16n8k16.row.col.f32.bf16.bf16.f32 "
                 "{%0,%1,%2,%3}, {%4,%5,%6,%7}, {%8,%9}, {%0,%1,%2,%3};"
                 : "+f"(c0), "+f"(c1), "+f"(c2), "+f"(c3)
                 : "r"(a0), "r"(a1), "r"(a2), "r"(a3), "r"(b0), "r"(b1));
}
__device__ __forceinline__ void mma_e4m3(float& c0, float& c1, float& c2, float& c3,
                                         unsigned a0, unsigned a1, unsigned a2, unsigned a3,
                                         unsigned b0, unsigned b1) {
    asm volatile("mma.sync.aligned.m16n8k32.row.col.f32.e4m3.e4m3.f32 "
                 "{%0,%1,%2,%3}, {%4,%5,%6,%7}, {%8,%9}, {%0,%1,%2,%3};"
                 : "+f"(c0), "+f"(c1), "+f"(c2), "+f"(c3)
                 : "r"(a0), "r"(a1), "r"(a2), "r"(a3), "r"(b0), "r"(b1));
}

// =================================================================
// Kernel 1: qkv convs, 2 channels/block, 768 threads (3 px/thread),
// in-kernel epilogues. grid = (BB*64, 3): y 0=q, 1=k(norm), 2=v(fp8)
// (exact R9 winner version)
// =================================================================
__global__ __launch_bounds__(768) void qkv_kernel(
    const float* __restrict__ x,
    const float* __restrict__ wq, const float* __restrict__ wk, const float* __restrict__ wv,
    const float* __restrict__ dwq, const float* __restrict__ dwk, const float* __restrict__ dwv)
{
    __shared__ float sp[2][NTOK + 8];
    __shared__ float wp[2][32];
    __shared__ float wd[2][9];
    __shared__ float redw[2][24];
    __shared__ float s_sc[2];

    const int t  = blockIdx.y;
    const int b  = blockIdx.x >> 6;
    const int cp = blockIdx.x & 63;
    const int c0 = cp * 2;
    const int g  = c0 >> 5;
    const int tid = threadIdx.x;
    const int lane = tid & 31;

    const float* wsel = (t == 0) ? wq : (t == 1) ? wk : wv;
    const float* dsel = (t == 0) ? dwq : (t == 1) ? dwk : dwv;

    if (tid < 64) wp[tid >> 5][tid & 31] = wsel[(c0 + (tid >> 5))*32 + (tid & 31)];
    if (tid < 18) wd[tid / 9][tid % 9]   = dsel[(c0 + tid/9)*9 + tid % 9];
    __syncthreads();

    // pointwise grouped conv, 2 out-channels share x loads
    const float* xb = x + (size_t)(b*CC + g*32) * NTOK + tid;
    float a0[3], a1[3];
#pragma unroll
    for (int p = 0; p < 3; ++p) { a0[p] = 0.f; a1[p] = 0.f; }
    for (int i = 0; i < 32; ++i) {
        const float w0 = wp[0][i], w1 = wp[1][i];
        const float* xi = xb + (size_t)i*NTOK;
#pragma unroll
        for (int p = 0; p < 3; ++p) {
            float xv = xi[p*768];
            a0[p] += w0*xv; a1[p] += w1*xv;
        }
    }
#pragma unroll
    for (int p = 0; p < 3; ++p) { sp[0][tid + p*768] = a0[p]; sp[1][tid + p*768] = a1[p]; }
    __syncthreads();

    // depthwise 3x3 SAME + per-channel stat
    float d0[3], d1[3];
    float rv0 = 0.f, rv1 = 0.f;
#pragma unroll
    for (int p = 0; p < 3; ++p) {
        int n = tid + p*768;
        int r = n / HH;
        int col = n - r*HH;
        float s0 = 0.f, s1 = 0.f;
#pragma unroll
        for (int dy = 0; dy < 3; ++dy) {
            int rr = r + dy - 1;
            if ((unsigned)rr < (unsigned)HH) {
#pragma unroll
                for (int dx = 0; dx < 3; ++dx) {
                    int cc2 = col + dx - 1;
                    if ((unsigned)cc2 < (unsigned)HH) {
                        int nn = rr*HH + cc2;
                        int ki = dy*3 + dx;
                        s0 += wd[0][ki] * sp[0][nn];
                        s1 += wd[1][ki] * sp[1][nn];
                    }
                }
            }
        }
        d0[p] = s0; d1[p] = s1;
        if (t == 1)      { rv0 += s0*s0;                rv1 += s1*s1; }
        else if (t == 2) { rv0 = fmaxf(rv0, fabsf(s0)); rv1 = fmaxf(rv1, fabsf(s1)); }
    }

    float sc0 = 1.f, sc1 = 1.f;
    if (t != 0) {
#pragma unroll
        for (int off = 16; off; off >>= 1) {
            float o0 = __shfl_xor_sync(0xffffffffu, rv0, off);
            float o1 = __shfl_xor_sync(0xffffffffu, rv1, off);
            if (t == 1) { rv0 += o0; rv1 += o1; }
            else        { rv0 = fmaxf(rv0, o0); rv1 = fmaxf(rv1, o1); }
        }
        if (lane == 0) { redw[0][tid >> 5] = rv0; redw[1][tid >> 5] = rv1; }
        __syncthreads();
        if (tid < 32) {
            float v0 = (tid < 24) ? redw[0][tid] : 0.f;
            float v1 = (tid < 24) ? redw[1][tid] : 0.f;
#pragma unroll
            for (int off = 16; off; off >>= 1) {
                float o0 = __shfl_xor_sync(0xffffffffu, v0, off);
                float o1 = __shfl_xor_sync(0xffffffffu, v1, off);
                if (t == 1) { v0 += o0; v1 += o1; }
                else        { v0 = fmaxf(v0, o0); v1 = fmaxf(v1, o1); }
            }
            if (tid == 0) {
                if (t == 1) {
                    s_sc[0] = 1.f / fmaxf(sqrtf(v0), 1e-12f);
                    s_sc[1] = 1.f / fmaxf(sqrtf(v1), 1e-12f);
                } else {
                    s_sc[0] = (v0 > 0.f) ? 240.f / v0 : 0.f;
                    s_sc[1] = (v1 > 0.f) ? 240.f / v1 : 0.f;
                    g_vsinv[b*CC + c0]     = (v0 > 0.f) ? v0 / 240.f : 0.f;
                    g_vsinv[b*CC + c0 + 1] = (v1 > 0.f) ? v1 / 240.f : 0.f;
                }
            }
        }
        __syncthreads();
        sc0 = s_sc[0]; sc1 = s_sc[1];
    }

    if (t == 0) {
        __nv_bfloat16* q0 = g_q16 + (size_t)(b*CC + c0)*NTOK;
        __nv_bfloat16* q1 = g_q16 + (size_t)(b*CC + c0 + 1)*NTOK;
#pragma unroll
        for (int p = 0; p < 3; ++p) {
            int n = tid + p*768;
            q0[n] = __float2bfloat16(d0[p]);
            q1[n] = __float2bfloat16(d1[p]);
        }
    } else if (t == 1) {
        const int bh = b*NHEADS + (c0 >> 4);
        const int j  = (c0 & 15) >> 1;
        const int slot = sperm(j);
        __nv_bfloat16* kTp = g_kT + (size_t)bh*NTOK*CHH + slot*2;
#pragma unroll
        for (int p = 0; p < 3; ++p) {
            int n = tid + p*768;
            kTp[(size_t)n*16]     = __float2bfloat16(d0[p] * sc0);
            kTp[(size_t)n*16 + 1] = __float2bfloat16(d1[p] * sc1);
        }
    } else {
        unsigned char* v0 = g_v8 + (size_t)(b*CC + c0)*NTOK;
        unsigned char* v1 = g_v8 + (size_t)(b*CC + c0 + 1)*NTOK;
#pragma unroll
        for (int p = 0; p < 3; ++p) {
            int n = tid + p*768;
            int np = (n & ~31) | (sperm((n >> 2) & 7) * 4) | (n & 3);
            v0[np] = (unsigned char)f2e4m3(d0[p] * sc0);
            v1[np] = (unsigned char)f2e4m3(d1[p] * sc1);
        }
    }
}

// =================================================================
// Kernel 2: fused attention (R8/R9 winner shape: 512 threads, 2 CTA/SM)
// Change vs R9: FULL-row register cache rr[18] — select + softmax do
// zero smem score reads.
// grid = (144, 16)
// =================================================================
#define SROWB 2320
#define ATTN_SM_S   (16*SROWB)
#define ATTN_SM_QA  512
#define ATTN_SM_SCR (16*256*4)
#define ATTN_SM_ZS  (16*16*4)
#define ATTN_SMEM_BYTES (ATTN_SM_S + ATTN_SM_QA + ATTN_SM_SCR + ATTN_SM_ZS)

__global__ __launch_bounds__(512, 2) void attn_kernel(const float* __restrict__ temperature)
{
    extern __shared__ unsigned char smraw[];
    unsigned char* smS = smraw;
    __nv_bfloat16* qA  = (__nv_bfloat16*)(smraw + ATTN_SM_S);
    float* scratch     = (float*)(smraw + ATTN_SM_S + ATTN_SM_QA);
    float* zs          = (float*)(smraw + ATTN_SM_S + ATTN_SM_QA + ATTN_SM_SCR);

    const int rt = blockIdx.x, bh = blockIdx.y;
    const int b = bh >> 3, h = bh & 7;
    const int bc0 = b*CC + h*CHH;
    const int row0 = rt * 16;
    const int tid = threadIdx.x;
    const int w = tid >> 5, lane = tid & 31;
    const float ts = temperature[h];

    // ---- phase 0: Q rows, L2-normalize over C_h, fold temperature ----
    if (tid < 256) {
        int r = tid >> 4, c = tid & 15;
        float qv = __bfloat162float(g_q16[(size_t)(bc0 + c)*NTOK + row0 + r]);
        float ss = qv * qv;
#pragma unroll
        for (int off = 8; off; off >>= 1) ss += __shfl_xor_sync(0xffffffffu, ss, off, 16);
        float qt = qv * ts / fmaxf(sqrtf(ss), 1e-12f);
        qA[r*16 + c] = __float2bfloat16(qt);
    }
    __syncthreads();

    // ---- phase 1: scores via bf16 mma -> keymapped e4m3 smem ----
    {
        const unsigned* qAu = (const unsigned*)qA;
        int r = lane >> 2, kx = (lane & 3) * 2;
        unsigned a0 = qAu[(r*16 + kx) >> 1];
        unsigned a1 = qAu[((r+8)*16 + kx) >> 1];
        unsigned a2 = qAu[(r*16 + kx + 8) >> 1];
        unsigned a3 = qAu[((r+8)*16 + kx + 8) >> 1];

        const ull* kT64 = (const ull*)(g_kT + (size_t)bh * NTOK * CHH);
        const int jl = lane >> 2, ko = lane & 3;
        const int cst = (lane & 3) * 2;
#pragma unroll
        for (int mb = 0; mb < 3; ++mb) {
            ull rbb[6];
#pragma unroll
            for (int m = 0; m < 6; ++m) {
                int j0 = w*144 + (mb*6 + m)*8;
                rbb[m] = kT64[(size_t)(j0 + jl)*4 + ko];
            }
#pragma unroll
            for (int m = 0; m < 6; ++m) {
                int j0 = w*144 + (mb*6 + m)*8;
                float c0 = 0.f, c1 = 0.f, c2 = 0.f, c3 = 0.f;
                mma_bf16(c0, c1, c2, c3, a0, a1, a2, a3,
                         (unsigned)rbb[m], (unsigned)(rbb[m] >> 32));
                int off = j0 + cst;
                unsigned comb = (unsigned)pack2_e4m3(c0, c1)
                              | ((unsigned)pack2_e4m3(c2, c3) << 16);
                comb = keymap4(comb);
                *(unsigned short*)(smS + r*SROWB + off)     = (unsigned short)comb;
                *(unsigned short*)(smS + (r+8)*SROWB + off) = (unsigned short)(comb >> 16);
            }
        }
    }
    __syncthreads();

    // ---- phase 2: FULL-row register cache + 4-pass binary search ----
    unsigned* srowU = (unsigned*)(smS + (size_t)w * SROWB);
    unsigned rr[18];
#pragma unroll
    for (int it = 0; it < 18; ++it) rr[it] = srowU[lane + it*32];

    int lo = 0, hi = 15;
#pragma unroll
    for (int pass = 0; pass < 4; ++pass) {
        int mid = (lo + hi + 1) >> 1;
        unsigned t4 = (unsigned)(mid << 4) * 0x01010101u;
        int cnt = 0;
#pragma unroll
        for (int it = 0; it < 18; ++it)
            cnt = __dp4a((int)__vsetgeu4(rr[it], t4), 0x01010101, cnt);
#pragma unroll
        for (int off = 16; off; off >>= 1) cnt += __shfl_xor_sync(0xffffffffu, cnt, off);
        if (cnt >= KTOP) lo = mid; else hi = mid - 1;
    }
    const unsigned tk4 = ((unsigned)(lo << 4)) * 0x01010101u;

    // ---- phase 3: masked f16x2 softmax weights from registers, in place ----
    {
        const float l2ef = 1.4426950408889634f;
        const float shift = fabsf(ts);
        const __half2 hl2e = __float2half2_rn(l2ef);
        const __half2 hb   = __float2half2_rn(-shift * l2ef);
#pragma unroll
        for (int it = 0; it < 18; ++it) {
            unsigned k = rr[it];
            unsigned mff = __vcmpgeu4(k, tk4);
            unsigned sb = (k & 0x80808080u) >> 7;
            unsigned u = (~k) ^ (sb * 0x7Fu);
            unsigned hlo, hhi;
            asm("cvt.rn.f16x2.e4m3x2 %0, %1;" : "=r"(hlo) : "h"((unsigned short)(u & 0xffffu)));
            asm("cvt.rn.f16x2.e4m3x2 %0, %1;" : "=r"(hhi) : "h"((unsigned short)(u >> 16)));
            __half2 alo = __hfma2(*(__half2*)&hlo, hl2e, hb);
            __half2 ahi = __hfma2(*(__half2*)&hhi, hl2e, hb);
            unsigned wlo, whi;
            asm("ex2.approx.f16x2 %0, %1;" : "=r"(wlo) : "r"(*(unsigned*)&alo));
            asm("ex2.approx.f16x2 %0, %1;" : "=r"(whi) : "r"(*(unsigned*)&ahi));
            unsigned short plo, phi;
            asm("cvt.rn.satfinite.e4m3x2.f16x2 %0, %1;" : "=h"(plo) : "r"(wlo));
            asm("cvt.rn.satfinite.e4m3x2.f16x2 %0, %1;" : "=h"(phi) : "r"(whi));
            srowU[lane + it*32] = ((unsigned)plo | ((unsigned)phi << 16)) & mff;
        }
    }
    __syncthreads();

    // ---- phase 4: PV via fp8 mma (LDG.64 V) + ones-column mma for Z ----
    float acc[8];
#pragma unroll
    for (int i = 0; i < 8; ++i) acc[i] = 0.f;
    float za0 = 0.f, za1 = 0.f, za2 = 0.f, za3 = 0.f;
    {
        const unsigned char* vb = g_v8 + (size_t)bc0 * NTOK;
        const int r = lane >> 2, ko = lane & 3, kx = ko * 4;
        const int nn = lane >> 2;
        const unsigned bz = (lane < 4) ? 0x38383838u : 0u;   // e4m3 1.0 in col 0
        for (int k0 = w*32; k0 < NTOK; k0 += 512) {
            unsigned A0 = *(const unsigned*)(smS + r*SROWB + k0 + kx);
            unsigned A1 = *(const unsigned*)(smS + (r+8)*SROWB + k0 + kx);
            unsigned A2 = *(const unsigned*)(smS + r*SROWB + k0 + kx + 16);
            unsigned A3 = *(const unsigned*)(smS + (r+8)*SROWB + k0 + kx + 16);
            ull bb01 = *(const ull*)(vb + (size_t)nn*NTOK + k0 + 8*ko);
            ull bb23 = *(const ull*)(vb + (size_t)(nn+8)*NTOK + k0 + 8*ko);
            mma_e4m3(acc[0], acc[1], acc[2], acc[3], A0, A1, A2, A3,
                     (unsigned)bb01, (unsigned)(bb01 >> 32));
            mma_e4m3(acc[4], acc[5], acc[6], acc[7], A0, A1, A2, A3,
                     (unsigned)bb23, (unsigned)(bb23 >> 32));
            mma_e4m3(za0, za1, za2, za3, A0, A1, A2, A3, bz, bz);
        }
    }
    {
        int r = lane >> 2, c2s = (lane & 3) * 2;
        float* sw = scratch + w*256;
        sw[r*16 + c2s]           = acc[0];
        sw[r*16 + c2s + 1]       = acc[1];
        sw[(r+8)*16 + c2s]       = acc[2];
        sw[(r+8)*16 + c2s + 1]   = acc[3];
        sw[r*16 + 8 + c2s]       = acc[4];
        sw[r*16 + 8 + c2s + 1]   = acc[5];
        sw[(r+8)*16 + 8 + c2s]   = acc[6];
        sw[(r+8)*16 + 8 + c2s+1] = acc[7];
        if ((lane & 3) == 0) {
            zs[w*16 + r]     = za0;
            zs[w*16 + 8 + r] = za2;
        }
    }
    __syncthreads();

    // ---- phase 5: cross-warp reduce, z-normalize, unscale, write ----
    if (tid < 256) {
        int r = tid >> 4, c = tid & 15;
        float s = 0.f, zr = 0.f;
#pragma unroll
        for (int wi = 0; wi < 16; ++wi) {
            s  += scratch[wi*256 + r*16 + c];
            zr += zs[wi*16 + r];
        }
        g_attn[(size_t)(bc0 + c)*NTOK + row0 + r] = s / zr * g_vsinv[bc0 + c];
    }
}

// =================================================================
// Kernel 3: out = x + wo @ attn via bf16 tensor cores.
// grid = (72, 2), 256 threads (8 warps; warp = 16 c_out rows)
// =================================================================
#define OC_STRIDE 136
#define OC_SMEM_BYTES ((128*OC_STRIDE + 32*OC_STRIDE) * 2)

__global__ __launch_bounds__(256) void outconv_kernel(
    const float* __restrict__ x, const float* __restrict__ wo, float* __restrict__ out)
{
    extern __shared__ __nv_bfloat16 smoc[];
    __nv_bfloat16* wos = smoc;                      // [128][136]
    __nv_bfloat16* ats = smoc + 128*OC_STRIDE;      // [32 tokens][136 channels]

    const int b  = blockIdx.y;
    const int n0 = blockIdx.x * 32;
    const int tid = threadIdx.x;

    for (int l = tid; l < 16384; l += 256)
        wos[(l >> 7)*OC_STRIDE + (l & 127)] = __float2bfloat16(wo[l]);
    for (int l = tid; l < 4096; l += 256) {
        int c = l >> 5, nl = l & 31;
        ats[nl*OC_STRIDE + c] = __float2bfloat16(g_attn[(size_t)(b*CC + c)*NTOK + n0 + nl]);
    }
    __syncthreads();

    const int w = tid >> 5, lane = tid & 31;
    const int r = lane >> 2, kq = (lane & 3) * 2;

    float acc[4][4];
#pragma unroll
    for (int ng = 0; ng < 4; ++ng)
#pragma unroll
        for (int i = 0; i < 4; ++i) acc[ng][i] = 0.f;

#pragma unroll
    for (int kc = 0; kc < 8; ++kc) {
        const int k0 = kc * 16;
        unsigned a0 = *(const unsigned*)&wos[(w*16 + r)*OC_STRIDE + k0 + kq];
        unsigned a1 = *(const unsigned*)&wos[(w*16 + r + 8)*OC_STRIDE + k0 + kq];
        unsigned a2 = *(const unsigned*)&wos[(w*16 + r)*OC_STRIDE + k0 + kq + 8];
        unsigned a3 = *(const unsigned*)&wos[(w*16 + r + 8)*OC_STRIDE + k0 + kq + 8];
#pragma unroll
        for (int ng = 0; ng < 4; ++ng) {
            unsigned b0 = *(const unsigned*)&ats[(ng*8 + r)*OC_STRIDE + k0 + kq];
            unsigned b1 = *(const unsigned*)&ats[(ng*8 + r)*OC_STRIDE + k0 + kq + 8];
            mma_bf16(acc[ng][0], acc[ng][1], acc[ng][2], acc[ng][3],
                     a0, a1, a2, a3, b0, b1);
        }
    }

#pragma unroll
    for (int ng = 0; ng < 4; ++ng) {
        const int col = n0 + ng*8 + kq;
        size_t i0 = (size_t)(b*CC + w*16 + r)*NTOK + col;
        float2 x0 = *(const float2*)(x + i0);
        *(float2*)(out + i0) = make_float2(x0.x + acc[ng][0], x0.y + acc[ng][1]);
        size_t i1 = (size_t)(b*CC + w*16 + r + 8)*NTOK + col;
        float2 x1 = *(const float2*)(x + i1);
        *(float2*)(out + i1) = make_float2(x1.x + acc[ng][2], x1.y + acc[ng][3]);
    }
}

// =================================================================
extern "C" void kernel_launch(void* const* d_in, const int* in_sizes, int n_in,
                              void* d_out, int out_size)
{
    const float* x    = (const float*)d_in[0];
    const float* wq   = (const float*)d_in[1];
    const float* wk   = (const float*)d_in[2];
    const float* wv   = (const float*)d_in[3];
    const float* dwq  = (const float*)d_in[4];
    const float* dwk  = (const float*)d_in[5];
    const float* dwv  = (const float*)d_in[6];
    const float* wo   = (const float*)d_in[7];
    const float* temp = (const float*)d_in[8];
    float* out = (float*)d_out;

    cudaFuncSetAttribute(attn_kernel, cudaFuncAttributeMaxDynamicSharedMemorySize, ATTN_SMEM_BYTES);
    cudaFuncSetAttribute(outconv_kernel, cudaFuncAttributeMaxDynamicSharedMemorySize, OC_SMEM_BYTES);

    qkv_kernel<<<dim3(BB*64, 3), 768>>>(x, wq, wk, wv, dwq, dwk, dwv);
    attn_kernel<<<dim3(NTOK/16, BB*NHEADS), 512, ATTN_SMEM_BYTES>>>(temp);
    outconv_kernel<<<dim3(NTOK/32, BB), 256, OC_SMEM_BYTES>>>(x, wo, out);
}

// round 12
// speedup vs baseline: 1.0430x; 1.0014x over previous
#include <cuda_runtime.h>
#include <cuda_bf16.h>
#include <cuda_fp16.h>
#include <cuda_fp8.h>
#include <cstdint>

#define BB   2
#define CC   128
#define HH   48
#define NTOK 2304
#define NHEADS 8
#define CHH  16
#define KTOP 1843

typedef unsigned long long ull;

// ---------------- scratch ----------------
__device__ __nv_bfloat16 g_q16[BB*CC*NTOK];          // raw q bf16, [b*C+c][n]
__device__ __nv_bfloat16 g_kT[BB*NHEADS*NTOK*CHH];   // NORMALIZED K, [bh][n][ch-pair-permuted]
__device__ unsigned char g_v8[BB*CC*NTOK];           // v e4m3 (scaled), token-pair-permuted
__device__ float g_vsinv[BB*CC];                     // per-channel V inverse scale
__device__ float g_attn[BB*CC*NTOK];

// ---------------- fp8 helpers ----------------
__device__ __forceinline__ unsigned short pack2_e4m3(float lo, float hi) {
    unsigned short r;
    asm("cvt.rn.satfinite.e4m3x2.f32 %0, %1, %2;" : "=h"(r) : "f"(hi), "f"(lo));
    return r;
}
__device__ __forceinline__ unsigned f2e4m3(float f) {
    return (unsigned)__nv_cvt_float_to_fp8(f, __NV_SATFINITE, __NV_E4M3);
}
// monotone byte keymap over 4 packed e4m3 (forward)
__device__ __forceinline__ unsigned keymap4(unsigned u) {
    unsigned m = u & 0x80808080u;
    unsigned X = 0x80808080u | ((m >> 7) * 0x7Fu);
    return u ^ X;
}
// pair-permute slot map: u32 j (0..7) -> slot (pairs (j, j+4) adjacent)
__device__ __forceinline__ int sperm(int j) { return (j < 4) ? 2*j : 2*j - 7; }

// ---------------- mma wrappers ----------------
__device__ __forceinline__ void mma_bf16(float& c0, float& c1, float& c2, float& c3,
                                         unsigned a0, unsigned a1, unsigned a2, unsigned a3,
                                         unsigned b0, unsigned b1) {
    asm volatile("mma.sync.aligned.m16n8k16.row.col.f32.bf16.bf16.f32 "
                 "{%0,%1,%2,%3}, {%4,%5,%6,%7}, {%8,%9}, {%0,%1,%2,%3};"
                 : "+f"(c0), "+f"(c1), "+f"(c2), "+f"(c3)
                 : "r"(a0), "r"(a1), "r"(a2), "r"(a3), "r"(b0), "r"(b1));
}
__device__ __forceinline__ void mma_e4m3(float& c0, float& c1, float& c2, float& c3,
                                         unsigned a0, unsigned a1, unsigned a2, unsigned a3,
                                         unsigned b0, unsigned b1) {
    asm volatile("mma.sync.aligned.m16n8k32.row.col.f32.e4m3.e4m3.f32 "
                 "{%0,%1,%2,%3}, {%4,%5,%6,%7}, {%8,%9}, {%0,%1,%2,%3};"
                 : "+f"(c0), "+f"(c1), "+f"(c2), "+f"(c3)
                 : "r"(a0), "r"(a1), "r"(a2), "r"(a3), "r"(b0), "r"(b1));
}

// =================================================================
// Kernel 1: qkv convs (exact R9 winner version)
// =================================================================
__global__ __launch_bounds__(768) void qkv_kernel(
    const float* __restrict__ x,
    const float* __restrict__ wq, const float* __restrict__ wk, const float* __restrict__ wv,
    const float* __restrict__ dwq, const float* __restrict__ dwk, const float* __restrict__ dwv)
{
    __shared__ float sp[2][NTOK + 8];
    __shared__ float wp[2][32];
    __shared__ float wd[2][9];
    __shared__ float redw[2][24];
    __shared__ float s_sc[2];

    const int t  = blockIdx.y;
    const int b  = blockIdx.x >> 6;
    const int cp = blockIdx.x & 63;
    const int c0 = cp * 2;
    const int g  = c0 >> 5;
    const int tid = threadIdx.x;
    const int lane = tid & 31;

    const float* wsel = (t == 0) ? wq : (t == 1) ? wk : wv;
    const float* dsel = (t == 0) ? dwq : (t == 1) ? dwk : dwv;

    if (tid < 64) wp[tid >> 5][tid & 31] = wsel[(c0 + (tid >> 5))*32 + (tid & 31)];
    if (tid < 18) wd[tid / 9][tid % 9]   = dsel[(c0 + tid/9)*9 + tid % 9];
    __syncthreads();

    const float* xb = x + (size_t)(b*CC + g*32) * NTOK + tid;
    float a0[3], a1[3];
#pragma unroll
    for (int p = 0; p < 3; ++p) { a0[p] = 0.f; a1[p] = 0.f; }
    for (int i = 0; i < 32; ++i) {
        const float w0 = wp[0][i], w1 = wp[1][i];
        const float* xi = xb + (size_t)i*NTOK;
#pragma unroll
        for (int p = 0; p < 3; ++p) {
            float xv = xi[p*768];
            a0[p] += w0*xv; a1[p] += w1*xv;
        }
    }
#pragma unroll
    for (int p = 0; p < 3; ++p) { sp[0][tid + p*768] = a0[p]; sp[1][tid + p*768] = a1[p]; }
    __syncthreads();

    float d0[3], d1[3];
    float rv0 = 0.f, rv1 = 0.f;
#pragma unroll
    for (int p = 0; p < 3; ++p) {
        int n = tid + p*768;
        int r = n / HH;
        int col = n - r*HH;
        float s0 = 0.f, s1 = 0.f;
#pragma unroll
        for (int dy = 0; dy < 3; ++dy) {
            int rr = r + dy - 1;
            if ((unsigned)rr < (unsigned)HH) {
#pragma unroll
                for (int dx = 0; dx < 3; ++dx) {
                    int cc2 = col + dx - 1;
                    if ((unsigned)cc2 < (unsigned)HH) {
                        int nn = rr*HH + cc2;
                        int ki = dy*3 + dx;
                        s0 += wd[0][ki] * sp[0][nn];
                        s1 += wd[1][ki] * sp[1][nn];
                    }
                }
            }
        }
        d0[p] = s0; d1[p] = s1;
        if (t == 1)      { rv0 += s0*s0;                rv1 += s1*s1; }
        else if (t == 2) { rv0 = fmaxf(rv0, fabsf(s0)); rv1 = fmaxf(rv1, fabsf(s1)); }
    }

    float sc0 = 1.f, sc1 = 1.f;
    if (t != 0) {
#pragma unroll
        for (int off = 16; off; off >>= 1) {
            float o0 = __shfl_xor_sync(0xffffffffu, rv0, off);
            float o1 = __shfl_xor_sync(0xffffffffu, rv1, off);
            if (t == 1) { rv0 += o0; rv1 += o1; }
            else        { rv0 = fmaxf(rv0, o0); rv1 = fmaxf(rv1, o1); }
        }
        if (lane == 0) { redw[0][tid >> 5] = rv0; redw[1][tid >> 5] = rv1; }
        __syncthreads();
        if (tid < 32) {
            float v0 = (tid < 24) ? redw[0][tid] : 0.f;
            float v1 = (tid < 24) ? redw[1][tid] : 0.f;
#pragma unroll
            for (int off = 16; off; off >>= 1) {
                float o0 = __shfl_xor_sync(0xffffffffu, v0, off);
                float o1 = __shfl_xor_sync(0xffffffffu, v1, off);
                if (t == 1) { v0 += o0; v1 += o1; }
                else        { v0 = fmaxf(v0, o0); v1 = fmaxf(v1, o1); }
            }
            if (tid == 0) {
                if (t == 1) {
                    s_sc[0] = 1.f / fmaxf(sqrtf(v0), 1e-12f);
                    s_sc[1] = 1.f / fmaxf(sqrtf(v1), 1e-12f);
                } else {
                    s_sc[0] = (v0 > 0.f) ? 240.f / v0 : 0.f;
                    s_sc[1] = (v1 > 0.f) ? 240.f / v1 : 0.f;
                    g_vsinv[b*CC + c0]     = (v0 > 0.f) ? v0 / 240.f : 0.f;
                    g_vsinv[b*CC + c0 + 1] = (v1 > 0.f) ? v1 / 240.f : 0.f;
                }
            }
        }
        __syncthreads();
        sc0 = s_sc[0]; sc1 = s_sc[1];
    }

    if (t == 0) {
        __nv_bfloat16* q0 = g_q16 + (size_t)(b*CC + c0)*NTOK;
        __nv_bfloat16* q1 = g_q16 + (size_t)(b*CC + c0 + 1)*NTOK;
#pragma unroll
        for (int p = 0; p < 3; ++p) {
            int n = tid + p*768;
            q0[n] = __float2bfloat16(d0[p]);
            q1[n] = __float2bfloat16(d1[p]);
        }
    } else if (t == 1) {
        const int bh = b*NHEADS + (c0 >> 4);
        const int j  = (c0 & 15) >> 1;
        const int slot = sperm(j);
        __nv_bfloat16* kTp = g_kT + (size_t)bh*NTOK*CHH + slot*2;
#pragma unroll
        for (int p = 0; p < 3; ++p) {
            int n = tid + p*768;
            kTp[(size_t)n*16]     = __float2bfloat16(d0[p] * sc0);
            kTp[(size_t)n*16 + 1] = __float2bfloat16(d1[p] * sc1);
        }
    } else {
        unsigned char* v0 = g_v8 + (size_t)(b*CC + c0)*NTOK;
        unsigned char* v1 = g_v8 + (size_t)(b*CC + c0 + 1)*NTOK;
#pragma unroll
        for (int p = 0; p < 3; ++p) {
            int n = tid + p*768;
            int np = (n & ~31) | (sperm((n >> 2) & 7) * 4) | (n & 3);
            v0[np] = (unsigned char)f2e4m3(d0[p] * sc0);
            v1[np] = (unsigned char)f2e4m3(d1[p] * sc1);
        }
    }
}

// =================================================================
// Kernel 2: fused attention, 32-row CTA, two-tile software pipeline.
//  P1(A); sync; P1(B)+P23(A); sync; P4(A)+P23(B); sync; P5(A)+P4(B);
//  sync; P5(B).  512 threads, 2 CTA/SM.
// grid = (72, 16)
// =================================================================
#define SROWB 2320
#define ATTN_SM_S   (32*SROWB)              // 74240 (both tiles)
#define ATTN_SM_QA  1024                    // 32x16 bf16
#define ATTN_SM_SCR (2*16*256*4)            // 32768 (per-tile scratch)
#define ATTN_SM_ZS  (2*16*16*4)             // 2048
#define ATTN_SMEM_BYTES (ATTN_SM_S + ATTN_SM_QA + ATTN_SM_SCR + ATTN_SM_ZS)  // 110080

__global__ __launch_bounds__(512, 2) void attn_kernel(const float* __restrict__ temperature)
{
    extern __shared__ unsigned char smraw[];
    unsigned char* smS = smraw;
    __nv_bfloat16* qA  = (__nv_bfloat16*)(smraw + ATTN_SM_S);
    float* scratch     = (float*)(smraw + ATTN_SM_S + ATTN_SM_QA);          // [2][16][256]
    float* zs          = (float*)(smraw + ATTN_SM_S + ATTN_SM_QA + ATTN_SM_SCR); // [2][16][16]

    const int rt = blockIdx.x, bh = blockIdx.y;
    const int b = bh >> 3, h = bh & 7;
    const int bc0 = b*CC + h*CHH;
    const int row0 = rt * 32;
    const int tid = threadIdx.x;
    const int w = tid >> 5, lane = tid & 31;
    const float ts = temperature[h];

    // ---- P0: 32 Q rows, L2-normalize over C_h, fold temperature ----
    {
        int r = tid >> 4, c = tid & 15;
        float qv = __bfloat162float(g_q16[(size_t)(bc0 + c)*NTOK + row0 + r]);
        float ss = qv * qv;
#pragma unroll
        for (int off = 8; off; off >>= 1) ss += __shfl_xor_sync(0xffffffffu, ss, off, 16);
        float qt = qv * ts / fmaxf(sqrtf(ss), 1e-12f);
        qA[r*16 + c] = __float2bfloat16(qt);
    }
    __syncthreads();

    // ---- phase lambdas ----
    auto phase1 = [&](int t) {
        const unsigned* qAu = (const unsigned*)qA + t*128;
        int r = lane >> 2, kx = (lane & 3) * 2;
        unsigned a0 = qAu[(r*16 + kx) >> 1];
        unsigned a1 = qAu[((r+8)*16 + kx) >> 1];
        unsigned a2 = qAu[(r*16 + kx + 8) >> 1];
        unsigned a3 = qAu[((r+8)*16 + kx + 8) >> 1];

        unsigned char* smT = smS + (size_t)t*16*SROWB;
        const ull* kT64 = (const ull*)(g_kT + (size_t)bh * NTOK * CHH);
        const int jl = lane >> 2, ko = lane & 3;
        const int cst = (lane & 3) * 2;
#pragma unroll
        for (int mb = 0; mb < 3; ++mb) {
            ull rbb[6];
#pragma unroll
            for (int m = 0; m < 6; ++m) {
                int j0 = w*144 + (mb*6 + m)*8;
                rbb[m] = kT64[(size_t)(j0 + jl)*4 + ko];
            }
#pragma unroll
            for (int m = 0; m < 6; ++m) {
                int j0 = w*144 + (mb*6 + m)*8;
                float c0 = 0.f, c1 = 0.f, c2 = 0.f, c3 = 0.f;
                mma_bf16(c0, c1, c2, c3, a0, a1, a2, a3,
                         (unsigned)rbb[m], (unsigned)(rbb[m] >> 32));
                int off = j0 + cst;
                unsigned comb = (unsigned)pack2_e4m3(c0, c1)
                              | ((unsigned)pack2_e4m3(c2, c3) << 16);
                comb = keymap4(comb);
                *(unsigned short*)(smT + r*SROWB + off)     = (unsigned short)comb;
                *(unsigned short*)(smT + (r+8)*SROWB + off) = (unsigned short)(comb >> 16);
            }
        }
    };

    auto phase23 = [&](int t) {
        unsigned* srowU = (unsigned*)(smS + (size_t)(t*16 + w) * SROWB);
        unsigned rr[9];
#pragma unroll
        for (int it = 0; it < 9; ++it) rr[it] = srowU[lane + it*32];

        int lo = 0, hi = 15;
#pragma unroll
        for (int pass = 0; pass < 4; ++pass) {
            int mid = (lo + hi + 1) >> 1;
            unsigned t4 = (unsigned)(mid << 4) * 0x01010101u;
            int cnt = 0;
#pragma unroll
            for (int it = 0; it < 9; ++it)
                cnt = __dp4a((int)__vsetgeu4(rr[it], t4), 0x01010101, cnt);
#pragma unroll
            for (int it = 9; it < 18; ++it)
                cnt = __dp4a((int)__vsetgeu4(srowU[lane + it*32], t4), 0x01010101, cnt);
#pragma unroll
            for (int off = 16; off; off >>= 1) cnt += __shfl_xor_sync(0xffffffffu, cnt, off);
            if (cnt >= KTOP) lo = mid; else hi = mid - 1;
        }
        const unsigned tk4 = ((unsigned)(lo << 4)) * 0x01010101u;

        const float l2ef = 1.4426950408889634f;
        const float shift = fabsf(ts);
        const __half2 hl2e = __float2half2_rn(l2ef);
        const __half2 hb   = __float2half2_rn(-shift * l2ef);
#pragma unroll
        for (int it = 0; it < 18; ++it) {
            unsigned k = (it < 9) ? rr[it] : srowU[lane + it*32];
            unsigned mff = __vcmpgeu4(k, tk4);
            unsigned sb = (k & 0x80808080u) >> 7;
            unsigned u = (~k) ^ (sb * 0x7Fu);
            unsigned hlo, hhi;
            asm("cvt.rn.f16x2.e4m3x2 %0, %1;" : "=r"(hlo) : "h"((unsigned short)(u & 0xffffu)));
            asm("cvt.rn.f16x2.e4m3x2 %0, %1;" : "=r"(hhi) : "h"((unsigned short)(u >> 16)));
            __half2 alo = __hfma2(*(__half2*)&hlo, hl2e, hb);
            __half2 ahi = __hfma2(*(__half2*)&hhi, hl2e, hb);
            unsigned wlo, whi;
            asm("ex2.approx.f16x2 %0, %1;" : "=r"(wlo) : "r"(*(unsigned*)&alo));
            asm("ex2.approx.f16x2 %0, %1;" : "=r"(whi) : "r"(*(unsigned*)&ahi));
            unsigned short plo, phi;
            asm("cvt.rn.satfinite.e4m3x2.f16x2 %0, %1;" : "=h"(plo) : "r"(wlo));
            asm("cvt.rn.satfinite.e4m3x2.f16x2 %0, %1;" : "=h"(phi) : "r"(whi));
            srowU[lane + it*32] = ((unsigned)plo | ((unsigned)phi << 16)) & mff;
        }
    };

    auto phase4 = [&](int t) {
        float acc[8];
#pragma unroll
        for (int i = 0; i < 8; ++i) acc[i] = 0.f;
        float za0 = 0.f, za1 = 0.f, za2 = 0.f, za3 = 0.f;
        {
            unsigned char* smT = smS + (size_t)t*16*SROWB;
            const unsigned char* vb = g_v8 + (size_t)bc0 * NTOK;
            const int r = lane >> 2, ko = lane & 3, kx = ko * 4;
            const int nn = lane >> 2;
            const unsigned bz = (lane < 4) ? 0x38383838u : 0u;   // e4m3 1.0 in col 0
            for (int k0 = w*32; k0 < NTOK; k0 += 512) {
                unsigned A0 = *(const unsigned*)(smT + r*SROWB + k0 + kx);
                unsigned A1 = *(const unsigned*)(smT + (r+8)*SROWB + k0 + kx);
                unsigned A2 = *(const unsigned*)(smT + r*SROWB + k0 + kx + 16);
                unsigned A3 = *(const unsigned*)(smT + (r+8)*SROWB + k0 + kx + 16);
                ull bb01 = *(const ull*)(vb + (size_t)nn*NTOK + k0 + 8*ko);
                ull bb23 = *(const ull*)(vb + (size_t)(nn+8)*NTOK + k0 + 8*ko);
                mma_e4m3(acc[0], acc[1], acc[2], acc[3], A0, A1, A2, A3,
                         (unsigned)bb01, (unsigned)(bb01 >> 32));
                mma_e4m3(acc[4], acc[5], acc[6], acc[7], A0, A1, A2, A3,
                         (unsigned)bb23, (unsigned)(bb23 >> 32));
                mma_e4m3(za0, za1, za2, za3, A0, A1, A2, A3, bz, bz);
            }
        }
        {
            int r = lane >> 2, c2s = (lane & 3) * 2;
            float* sw = scratch + t*4096 + w*256;
            sw[r*16 + c2s]           = acc[0];
            sw[r*16 + c2s + 1]       = acc[1];
            sw[(r+8)*16 + c2s]       = acc[2];
            sw[(r+8)*16 + c2s + 1]   = acc[3];
            sw[r*16 + 8 + c2s]       = acc[4];
            sw[r*16 + 8 + c2s + 1]   = acc[5];
            sw[(r+8)*16 + 8 + c2s]   = acc[6];
            sw[(r+8)*16 + 8 + c2s+1] = acc[7];
            if ((lane & 3) == 0) {
                zs[t*256 + w*16 + r]     = za0;
                zs[t*256 + w*16 + 8 + r] = za2;
            }
        }
    };

    auto phase5 = [&](int t) {
        if (tid < 256) {
            int r = tid >> 4, c = tid & 15;
            float s = 0.f, zr = 0.f;
#pragma unroll
            for (int wi = 0; wi < 16; ++wi) {
                s  += scratch[t*4096 + wi*256 + r*16 + c];
                zr += zs[t*256 + wi*16 + r];
            }
            g_attn[(size_t)(bc0 + c)*NTOK + row0 + t*16 + r] = s / zr * g_vsinv[bc0 + c];
        }
    };

    // ---- pipelined schedule ----
    phase1(0);
    __syncthreads();
    phase1(1);
    phase23(0);
    __syncthreads();
    phase4(0);
    phase23(1);
    __syncthreads();
    phase5(0);
    phase4(1);
    __syncthreads();
    phase5(1);
}

// =================================================================
// Kernel 3: out = x + wo @ attn via bf16 tensor cores (R9 version)
// =================================================================
#define OC_STRIDE 136
#define OC_SMEM_BYTES ((128*OC_STRIDE + 32*OC_STRIDE) * 2)

__global__ __launch_bounds__(256) void outconv_kernel(
    const float* __restrict__ x, const float* __restrict__ wo, float* __restrict__ out)
{
    extern __shared__ __nv_bfloat16 smoc[];
    __nv_bfloat16* wos = smoc;                      // [128][136]
    __nv_bfloat16* ats = smoc + 128*OC_STRIDE;      // [32 tokens][136 channels]

    const int b  = blockIdx.y;
    const int n0 = blockIdx.x * 32;
    const int tid = threadIdx.x;

    for (int l = tid; l < 16384; l += 256)
        wos[(l >> 7)*OC_STRIDE + (l & 127)] = __float2bfloat16(wo[l]);
    for (int l = tid; l < 4096; l += 256) {
        int c = l >> 5, nl = l & 31;
        ats[nl*OC_STRIDE + c] = __float2bfloat16(g_attn[(size_t)(b*CC + c)*NTOK + n0 + nl]);
    }
    __syncthreads();

    const int w = tid >> 5, lane = tid & 31;
    const int r = lane >> 2, kq = (lane & 3) * 2;

    float acc[4][4];
#pragma unroll
    for (int ng = 0; ng < 4; ++ng)
#pragma unroll
        for (int i = 0; i < 4; ++i) acc[ng][i] = 0.f;

#pragma unroll
    for (int kc = 0; kc < 8; ++kc) {
        const int k0 = kc * 16;
        unsigned a0 = *(const unsigned*)&wos[(w*16 + r)*OC_STRIDE + k0 + kq];
        unsigned a1 = *(const unsigned*)&wos[(w*16 + r + 8)*OC_STRIDE + k0 + kq];
        unsigned a2 = *(const unsigned*)&wos[(w*16 + r)*OC_STRIDE + k0 + kq + 8];
        unsigned a3 = *(const unsigned*)&wos[(w*16 + r + 8)*OC_STRIDE + k0 + kq + 8];
#pragma unroll
        for (int ng = 0; ng < 4; ++ng) {
            unsigned b0 = *(const unsigned*)&ats[(ng*8 + r)*OC_STRIDE + k0 + kq];
            unsigned b1 = *(const unsigned*)&ats[(ng*8 + r)*OC_STRIDE + k0 + kq + 8];
            mma_bf16(acc[ng][0], acc[ng][1], acc[ng][2], acc[ng][3],
                     a0, a1, a2, a3, b0, b1);
        }
    }

#pragma unroll
    for (int ng = 0; ng < 4; ++ng) {
        const int col = n0 + ng*8 + kq;
        size_t i0 = (size_t)(b*CC + w*16 + r)*NTOK + col;
        float2 x0 = *(const float2*)(x + i0);
        *(float2*)(out + i0) = make_float2(x0.x + acc[ng][0], x0.y + acc[ng][1]);
        size_t i1 = (size_t)(b*CC + w*16 + r + 8)*NTOK + col;
        float2 x1 = *(const float2*)(x + i1);
        *(float2*)(out + i1) = make_float2(x1.x + acc[ng][2], x1.y + acc[ng][3]);
    }
}

// =================================================================
extern "C" void kernel_launch(void* const* d_in, const int* in_sizes, int n_in,
                              void* d_out, int out_size)
{
    const float* x    = (const float*)d_in[0];
    const float* wq   = (const float*)d_in[1];
    const float* wk   = (const float*)d_in[2];
    const float* wv   = (const float*)d_in[3];
    const float* dwq  = (const float*)d_in[4];
    const float* dwk  = (const float*)d_in[5];
    const float* dwv  = (const float*)d_in[6];
    const float* wo   = (const float*)d_in[7];
    const float* temp = (const float*)d_in[8];
    float* out = (float*)d_out;

    cudaFuncSetAttribute(attn_kernel, cudaFuncAttributeMaxDynamicSharedMemorySize, ATTN_SMEM_BYTES);
    cudaFuncSetAttribute(outconv_kernel, cudaFuncAttributeMaxDynamicSharedMemorySize, OC_SMEM_BYTES);

    qkv_kernel<<<dim3(BB*64, 3), 768>>>(x, wq, wk, wv, dwq, dwk, dwv);
    attn_kernel<<<dim3(NTOK/32, BB*NHEADS), 512, ATTN_SMEM_BYTES>>>(temp);
    outconv_kernel<<<dim3(NTOK/32, BB), 256, OC_SMEM_BYTES>>>(x, wo, out);
}

// round 13
// speedup vs baseline: 1.0763x; 1.0319x over previous
#include <cuda_runtime.h>
#include <cuda_bf16.h>
#include <cuda_fp16.h>
#include <cuda_fp8.h>
#include <cstdint>

#define BB   2
#define CC   128
#define HH   48
#define NTOK 2304
#define NHEADS 8
#define CHH  16
#define KTOP 1843

typedef unsigned long long ull;

// ---------------- scratch ----------------
__device__ __nv_bfloat16 g_q16[BB*CC*NTOK];          // raw q bf16, [b*C+c][n]
__device__ __nv_bfloat16 g_kT[BB*NHEADS*NTOK*CHH];   // NORMALIZED K, [bh][n][ch-pair-permuted]
__device__ unsigned char g_v8[BB*CC*NTOK];           // v e4m3 (scaled), token-pair-permuted
__device__ float g_vsinv[BB*CC];                     // per-channel V inverse scale
__device__ float g_attn[BB*CC*NTOK];

// ---------------- fp8 helpers ----------------
__device__ __forceinline__ unsigned short pack2_e4m3(float lo, float hi) {
    unsigned short r;
    asm("cvt.rn.satfinite.e4m3x2.f32 %0, %1, %2;" : "=h"(r) : "f"(hi), "f"(lo));
    return r;
}
__device__ __forceinline__ unsigned f2e4m3(float f) {
    return (unsigned)__nv_cvt_float_to_fp8(f, __NV_SATFINITE, __NV_E4M3);
}
// monotone byte keymap over 4 packed e4m3 (forward)
__device__ __forceinline__ unsigned keymap4(unsigned u) {
    unsigned m = u & 0x80808080u;
    unsigned X = 0x80808080u | ((m >> 7) * 0x7Fu);
    return u ^ X;
}
// pair-permute slot map: u32 j (0..7) -> slot (pairs (j, j+4) adjacent)
__device__ __forceinline__ int sperm(int j) { return (j < 4) ? 2*j : 2*j - 7; }

// ---------------- mma wrappers ----------------
__device__ __forceinline__ void mma_bf16(float& c0, float& c1, float& c2, float& c3,
                                         unsigned a0, unsigned a1, unsigned a2, unsigned a3,
                                         unsigned b0, unsigned b1) {
    asm volatile("mma.sync.aligned.m16n8k16.row.col.f32.bf16.bf16.f32 "
                 "{%0,%1,%2,%3}, {%4,%5,%6,%7}, {%8,%9}, {%0,%1,%2,%3};"
                 : "+f"(c0), "+f"(c1), "+f"(c2), "+f"(c3)
                 : "r"(a0), "r"(a1), "r"(a2), "r"(a3), "r"(b0), "r"(b1));
}
__device__ __forceinline__ void mma_e4m3(float& c0, float& c1, float& c2, float& c3,
                                         unsigned a0, unsigned a1, unsigned a2, unsigned a3,
                                         unsigned b0, unsigned b1) {
    asm volatile("mma.sync.aligned.m16n8k32.row.col.f32.e4m3.e4m3.f32 "
                 "{%0,%1,%2,%3}, {%4,%5,%6,%7}, {%8,%9}, {%0,%1,%2,%3};"
                 : "+f"(c0), "+f"(c1), "+f"(c2), "+f"(c3)
                 : "r"(a0), "r"(a1), "r"(a2), "r"(a3), "r"(b0), "r"(b1));
}

// =================================================================
// Kernel 1: FUSED qkv convs. One block = 2 channels x ALL 3 types.
// x group slice read ONCE. 768 threads, 3 px/thread, dynamic smem.
// grid = BB*64 blocks.
// Plane order: 0=q.c0 1=q.c1 2=k.c0 3=k.c1 4=v.c0 5=v.c1
// =================================================================
#define QKV_SPST (NTOK + 8)
#define QKV_SMEM_FLOATS (6*QKV_SPST + 6*32 + 6*9 + 4*24 + 4)
#define QKV_SMEM_BYTES  (QKV_SMEM_FLOATS * 4)

__global__ __launch_bounds__(768) void qkv_kernel(
    const float* __restrict__ x,
    const float* __restrict__ wq, const float* __restrict__ wk, const float* __restrict__ wv,
    const float* __restrict__ dwq, const float* __restrict__ dwk, const float* __restrict__ dwv)
{
    extern __shared__ float smq[];
    float* sp   = smq;                       // [6][QKV_SPST]
    float* wpp  = smq + 6*QKV_SPST;          // [6][32]
    float* wdd  = wpp + 6*32;                // [6][9]
    float* redw = wdd + 6*9;                 // [4][24]
    float* s_sc = redw + 4*24;               // [4]: kinv0, kinv1, vsc0, vsc1

    const int b  = blockIdx.x >> 6;
    const int cp = blockIdx.x & 63;
    const int c0 = cp * 2;
    const int g  = c0 >> 5;
    const int tid = threadIdx.x;
    const int lane = tid & 31;

    if (tid < 192) {
        int pl = tid >> 5, i = tid & 31;
        int ty = pl >> 1, oc = pl & 1;
        const float* w = (ty == 0) ? wq : (ty == 1) ? wk : wv;
        wpp[pl*32 + i] = w[(c0 + oc)*32 + i];
    }
    if (tid < 54) {
        int pl = tid / 9, ki = tid % 9;
        int ty = pl >> 1, oc = pl & 1;
        const float* dw = (ty == 0) ? dwq : (ty == 1) ? dwk : dwv;
        wdd[pl*9 + ki] = dw[(c0 + oc)*9 + ki];
    }
    __syncthreads();

    // pointwise grouped conv: x read once, 6 output planes
    const float* xb = x + (size_t)(b*CC + g*32) * NTOK + tid;
    float a[6][3];
#pragma unroll
    for (int pl = 0; pl < 6; ++pl)
#pragma unroll
        for (int p = 0; p < 3; ++p) a[pl][p] = 0.f;
    for (int i = 0; i < 32; ++i) {
        float xv[3];
        const float* xi = xb + (size_t)i*NTOK;
#pragma unroll
        for (int p = 0; p < 3; ++p) xv[p] = xi[p*768];
#pragma unroll
        for (int pl = 0; pl < 6; ++pl) {
            const float wv_ = wpp[pl*32 + i];
#pragma unroll
            for (int p = 0; p < 3; ++p) a[pl][p] += wv_ * xv[p];
        }
    }
#pragma unroll
    for (int pl = 0; pl < 6; ++pl)
#pragma unroll
        for (int p = 0; p < 3; ++p) sp[pl*QKV_SPST + tid + p*768] = a[pl][p];
    __syncthreads();

    // depthwise 3x3 SAME on all 6 planes + stats (k sumsq, v absmax)
    float d[6][3];
    float rv0 = 0.f, rv1 = 0.f, rv2 = 0.f, rv3 = 0.f;
#pragma unroll
    for (int p = 0; p < 3; ++p) {
        int n = tid + p*768;
        int r = n / HH;
        int col = n - r*HH;
        float s[6] = {0.f, 0.f, 0.f, 0.f, 0.f, 0.f};
#pragma unroll
        for (int dy = 0; dy < 3; ++dy) {
            int rr = r + dy - 1;
            if ((unsigned)rr < (unsigned)HH) {
#pragma unroll
                for (int dx = 0; dx < 3; ++dx) {
                    int cc2 = col + dx - 1;
                    if ((unsigned)cc2 < (unsigned)HH) {
                        int nn = rr*HH + cc2;
                        int ki = dy*3 + dx;
#pragma unroll
                        for (int pl = 0; pl < 6; ++pl)
                            s[pl] += wdd[pl*9 + ki] * sp[pl*QKV_SPST + nn];
                    }
                }
            }
        }
#pragma unroll
        for (int pl = 0; pl < 6; ++pl) d[pl][p] = s[pl];
        rv0 += s[2]*s[2];
        rv1 += s[3]*s[3];
        rv2 = fmaxf(rv2, fabsf(s[4]));
        rv3 = fmaxf(rv3, fabsf(s[5]));
    }

    // reductions: rv0/rv1 sum, rv2/rv3 max, across 24 warps
#pragma unroll
    for (int off = 16; off; off >>= 1) {
        rv0 += __shfl_xor_sync(0xffffffffu, rv0, off);
        rv1 += __shfl_xor_sync(0xffffffffu, rv1, off);
        rv2 = fmaxf(rv2, __shfl_xor_sync(0xffffffffu, rv2, off));
        rv3 = fmaxf(rv3, __shfl_xor_sync(0xffffffffu, rv3, off));
    }
    if (lane == 0) {
        int wi = tid >> 5;
        redw[0*24 + wi] = rv0;
        redw[1*24 + wi] = rv1;
        redw[2*24 + wi] = rv2;
        redw[3*24 + wi] = rv3;
    }
    __syncthreads();
    if (tid < 32) {
        float v0 = (tid < 24) ? redw[0*24 + tid] : 0.f;
        float v1 = (tid < 24) ? redw[1*24 + tid] : 0.f;
        float v2 = (tid < 24) ? redw[2*24 + tid] : 0.f;
        float v3 = (tid < 24) ? redw[3*24 + tid] : 0.f;
#pragma unroll
        for (int off = 16; off; off >>= 1) {
            v0 += __shfl_xor_sync(0xffffffffu, v0, off);
            v1 += __shfl_xor_sync(0xffffffffu, v1, off);
            v2 = fmaxf(v2, __shfl_xor_sync(0xffffffffu, v2, off));
            v3 = fmaxf(v3, __shfl_xor_sync(0xffffffffu, v3, off));
        }
        if (tid == 0) {
            s_sc[0] = 1.f / fmaxf(sqrtf(v0), 1e-12f);
            s_sc[1] = 1.f / fmaxf(sqrtf(v1), 1e-12f);
            s_sc[2] = (v2 > 0.f) ? 240.f / v2 : 0.f;
            s_sc[3] = (v3 > 0.f) ? 240.f / v3 : 0.f;
            g_vsinv[b*CC + c0]     = (v2 > 0.f) ? v2 / 240.f : 0.f;
            g_vsinv[b*CC + c0 + 1] = (v3 > 0.f) ? v3 / 240.f : 0.f;
        }
    }
    __syncthreads();
    const float ksc0 = s_sc[0], ksc1 = s_sc[1];
    const float vsc0 = s_sc[2], vsc1 = s_sc[3];

    // epilogues
    {   // q raw bf16
        __nv_bfloat16* q0 = g_q16 + (size_t)(b*CC + c0)*NTOK;
        __nv_bfloat16* q1 = g_q16 + (size_t)(b*CC + c0 + 1)*NTOK;
#pragma unroll
        for (int p = 0; p < 3; ++p) {
            int n = tid + p*768;
            q0[n] = __float2bfloat16(d[0][p]);
            q1[n] = __float2bfloat16(d[1][p]);
        }
    }
    {   // k normalized, pair-permuted channel slots
        const int bh = b*NHEADS + (c0 >> 4);
        const int j  = (c0 & 15) >> 1;
        const int slot = sperm(j);
        __nv_bfloat16* kTp = g_kT + (size_t)bh*NTOK*CHH + slot*2;
#pragma unroll
        for (int p = 0; p < 3; ++p) {
            int n = tid + p*768;
            kTp[(size_t)n*16]     = __float2bfloat16(d[2][p] * ksc0);
            kTp[(size_t)n*16 + 1] = __float2bfloat16(d[3][p] * ksc1);
        }
    }
    {   // v fp8, token-pair-permuted within 32-byte blocks
        unsigned char* v0 = g_v8 + (size_t)(b*CC + c0)*NTOK;
        unsigned char* v1 = g_v8 + (size_t)(b*CC + c0 + 1)*NTOK;
#pragma unroll
        for (int p = 0; p < 3; ++p) {
            int n = tid + p*768;
            int np = (n & ~31) | (sperm((n >> 2) & 7) * 4) | (n & 3);
            v0[np] = (unsigned char)f2e4m3(d[4][p] * vsc0);
            v1[np] = (unsigned char)f2e4m3(d[5][p] * vsc1);
        }
    }
}

// =================================================================
// Kernel 2: fused attention (exact R9 116.6us winner)
// grid = (144, 16), 512 threads, 2 CTA/SM
// =================================================================
#define SROWB 2320
#define ATTN_SM_S   (16*SROWB)
#define ATTN_SM_QA  512
#define ATTN_SM_SCR (16*256*4)
#define ATTN_SM_ZS  (16*16*4)
#define ATTN_SMEM_BYTES (ATTN_SM_S + ATTN_SM_QA + ATTN_SM_SCR + ATTN_SM_ZS)

__global__ __launch_bounds__(512, 2) void attn_kernel(const float* __restrict__ temperature)
{
    extern __shared__ unsigned char smraw[];
    unsigned char* smS = smraw;
    __nv_bfloat16* qA  = (__nv_bfloat16*)(smraw + ATTN_SM_S);
    float* scratch     = (float*)(smraw + ATTN_SM_S + ATTN_SM_QA);
    float* zs          = (float*)(smraw + ATTN_SM_S + ATTN_SM_QA + ATTN_SM_SCR);

    const int rt = blockIdx.x, bh = blockIdx.y;
    const int b = bh >> 3, h = bh & 7;
    const int bc0 = b*CC + h*CHH;
    const int row0 = rt * 16;
    const int tid = threadIdx.x;
    const int w = tid >> 5, lane = tid & 31;
    const float ts = temperature[h];

    // ---- phase 0: Q rows, L2-normalize over C_h, fold temperature ----
    if (tid < 256) {
        int r = tid >> 4, c = tid & 15;
        float qv = __bfloat162float(g_q16[(size_t)(bc0 + c)*NTOK + row0 + r]);
        float ss = qv * qv;
#pragma unroll
        for (int off = 8; off; off >>= 1) ss += __shfl_xor_sync(0xffffffffu, ss, off, 16);
        float qt = qv * ts / fmaxf(sqrtf(ss), 1e-12f);
        qA[r*16 + c] = __float2bfloat16(qt);
    }
    __syncthreads();

    // ---- phase 1: scores via bf16 mma -> keymapped e4m3 smem ----
    {
        const unsigned* qAu = (const unsigned*)qA;
        int r = lane >> 2, kx = (lane & 3) * 2;
        unsigned a0 = qAu[(r*16 + kx) >> 1];
        unsigned a1 = qAu[((r+8)*16 + kx) >> 1];
        unsigned a2 = qAu[(r*16 + kx + 8) >> 1];
        unsigned a3 = qAu[((r+8)*16 + kx + 8) >> 1];

        const ull* kT64 = (const ull*)(g_kT + (size_t)bh * NTOK * CHH);
        const int jl = lane >> 2, ko = lane & 3;
        const int cst = (lane & 3) * 2;
#pragma unroll
        for (int mb = 0; mb < 3; ++mb) {
            ull rbb[6];
#pragma unroll
            for (int m = 0; m < 6; ++m) {
                int j0 = w*144 + (mb*6 + m)*8;
                rbb[m] = kT64[(size_t)(j0 + jl)*4 + ko];
            }
#pragma unroll
            for (int m = 0; m < 6; ++m) {
                int j0 = w*144 + (mb*6 + m)*8;
                float c0 = 0.f, c1 = 0.f, c2 = 0.f, c3 = 0.f;
                mma_bf16(c0, c1, c2, c3, a0, a1, a2, a3,
                         (unsigned)rbb[m], (unsigned)(rbb[m] >> 32));
                int off = j0 + cst;
                unsigned comb = (unsigned)pack2_e4m3(c0, c1)
                              | ((unsigned)pack2_e4m3(c2, c3) << 16);
                comb = keymap4(comb);
                *(unsigned short*)(smS + r*SROWB + off)     = (unsigned short)comb;
                *(unsigned short*)(smS + (r+8)*SROWB + off) = (unsigned short)(comb >> 16);
            }
        }
    }
    __syncthreads();

    // ---- phase 2: half-row register cache + 4-pass binary search ----
    unsigned* srowU = (unsigned*)(smS + (size_t)w * SROWB);
    unsigned rr[9];
#pragma unroll
    for (int it = 0; it < 9; ++it) rr[it] = srowU[lane + it*32];

    int lo = 0, hi = 15;
#pragma unroll
    for (int pass = 0; pass < 4; ++pass) {
        int mid = (lo + hi + 1) >> 1;
        unsigned t4 = (unsigned)(mid << 4) * 0x01010101u;
        int cnt = 0;
#pragma unroll
        for (int it = 0; it < 9; ++it)
            cnt = __dp4a((int)__vsetgeu4(rr[it], t4), 0x01010101, cnt);
#pragma unroll
        for (int it = 9; it < 18; ++it)
            cnt = __dp4a((int)__vsetgeu4(srowU[lane + it*32], t4), 0x01010101, cnt);
#pragma unroll
        for (int off = 16; off; off >>= 1) cnt += __shfl_xor_sync(0xffffffffu, cnt, off);
        if (cnt >= KTOP) lo = mid; else hi = mid - 1;
    }
    const unsigned tk4 = ((unsigned)(lo << 4)) * 0x01010101u;

    // ---- phase 3: masked f16x2 softmax weights (shift by |ts|), in place ----
    {
        const float l2ef = 1.4426950408889634f;
        const float shift = fabsf(ts);
        const __half2 hl2e = __float2half2_rn(l2ef);
        const __half2 hb   = __float2half2_rn(-shift * l2ef);
#pragma unroll
        for (int it = 0; it < 18; ++it) {
            unsigned k = (it < 9) ? rr[it] : srowU[lane + it*32];
            unsigned mff = __vcmpgeu4(k, tk4);
            unsigned sb = (k & 0x80808080u) >> 7;
            unsigned u = (~k) ^ (sb * 0x7Fu);
            unsigned hlo, hhi;
            asm("cvt.rn.f16x2.e4m3x2 %0, %1;" : "=r"(hlo) : "h"((unsigned short)(u & 0xffffu)));
            asm("cvt.rn.f16x2.e4m3x2 %0, %1;" : "=r"(hhi) : "h"((unsigned short)(u >> 16)));
            __half2 alo = __hfma2(*(__half2*)&hlo, hl2e, hb);
            __half2 ahi = __hfma2(*(__half2*)&hhi, hl2e, hb);
            unsigned wlo, whi;
            asm("ex2.approx.f16x2 %0, %1;" : "=r"(wlo) : "r"(*(unsigned*)&alo));
            asm("ex2.approx.f16x2 %0, %1;" : "=r"(whi) : "r"(*(unsigned*)&ahi));
            unsigned short plo, phi;
            asm("cvt.rn.satfinite.e4m3x2.f16x2 %0, %1;" : "=h"(plo) : "r"(wlo));
            asm("cvt.rn.satfinite.e4m3x2.f16x2 %0, %1;" : "=h"(phi) : "r"(whi));
            srowU[lane + it*32] = ((unsigned)plo | ((unsigned)phi << 16)) & mff;
        }
    }
    __syncthreads();

    // ---- phase 4: PV via fp8 mma (LDG.64 V) + ones-column mma for Z ----
    float acc[8];
#pragma unroll
    for (int i = 0; i < 8; ++i) acc[i] = 0.f;
    float za0 = 0.f, za1 = 0.f, za2 = 0.f, za3 = 0.f;
    {
        const unsigned char* vb = g_v8 + (size_t)bc0 * NTOK;
        const int r = lane >> 2, ko = lane & 3, kx = ko * 4;
        const int nn = lane >> 2;
        const unsigned bz = (lane < 4) ? 0x38383838u : 0u;   // e4m3 1.0 in col 0
        for (int k0 = w*32; k0 < NTOK; k0 += 512) {
            unsigned A0 = *(const unsigned*)(smS + r*SROWB + k0 + kx);
            unsigned A1 = *(const unsigned*)(smS + (r+8)*SROWB + k0 + kx);
            unsigned A2 = *(const unsigned*)(smS + r*SROWB + k0 + kx + 16);
            unsigned A3 = *(const unsigned*)(smS + (r+8)*SROWB + k0 + kx + 16);
            ull bb01 = *(const ull*)(vb + (size_t)nn*NTOK + k0 + 8*ko);
            ull bb23 = *(const ull*)(vb + (size_t)(nn+8)*NTOK + k0 + 8*ko);
            mma_e4m3(acc[0], acc[1], acc[2], acc[3], A0, A1, A2, A3,
                     (unsigned)bb01, (unsigned)(bb01 >> 32));
            mma_e4m3(acc[4], acc[5], acc[6], acc[7], A0, A1, A2, A3,
                     (unsigned)bb23, (unsigned)(bb23 >> 32));
            mma_e4m3(za0, za1, za2, za3, A0, A1, A2, A3, bz, bz);
        }
    }
    {
        int r = lane >> 2, c2s = (lane & 3) * 2;
        float* sw = scratch + w*256;
        sw[r*16 + c2s]           = acc[0];
        sw[r*16 + c2s + 1]       = acc[1];
        sw[(r+8)*16 + c2s]       = acc[2];
        sw[(r+8)*16 + c2s + 1]   = acc[3];
        sw[r*16 + 8 + c2s]       = acc[4];
        sw[r*16 + 8 + c2s + 1]   = acc[5];
        sw[(r+8)*16 + 8 + c2s]   = acc[6];
        sw[(r+8)*16 + 8 + c2s+1] = acc[7];
        if ((lane & 3) == 0) {
            zs[w*16 + r]     = za0;
            zs[w*16 + 8 + r] = za2;
        }
    }
    __syncthreads();

    // ---- phase 5: cross-warp reduce, z-normalize, unscale, write ----
    if (tid < 256) {
        int r = tid >> 4, c = tid & 15;
        float s = 0.f, zr = 0.f;
#pragma unroll
        for (int wi = 0; wi < 16; ++wi) {
            s  += scratch[wi*256 + r*16 + c];
            zr += zs[wi*16 + r];
        }
        g_attn[(size_t)(bc0 + c)*NTOK + row0 + r] = s / zr * g_vsinv[bc0 + c];
    }
}

// =================================================================
// Kernel 3: out = x + wo @ attn via bf16 tensor cores (R9 version)
// =================================================================
#define OC_STRIDE 136
#define OC_SMEM_BYTES ((128*OC_STRIDE + 32*OC_STRIDE) * 2)

__global__ __launch_bounds__(256) void outconv_kernel(
    const float* __restrict__ x, const float* __restrict__ wo, float* __restrict__ out)
{
    extern __shared__ __nv_bfloat16 smoc[];
    __nv_bfloat16* wos = smoc;                      // [128][136]
    __nv_bfloat16* ats = smoc + 128*OC_STRIDE;      // [32 tokens][136 channels]

    const int b  = blockIdx.y;
    const int n0 = blockIdx.x * 32;
    const int tid = threadIdx.x;

    for (int l = tid; l < 16384; l += 256)
        wos[(l >> 7)*OC_STRIDE + (l & 127)] = __float2bfloat16(wo[l]);
    for (int l = tid; l < 4096; l += 256) {
        int c = l >> 5, nl = l & 31;
        ats[nl*OC_STRIDE + c] = __float2bfloat16(g_attn[(size_t)(b*CC + c)*NTOK + n0 + nl]);
    }
    __syncthreads();

    const int w = tid >> 5, lane = tid & 31;
    const int r = lane >> 2, kq = (lane & 3) * 2;

    float acc[4][4];
#pragma unroll
    for (int ng = 0; ng < 4; ++ng)
#pragma unroll
        for (int i = 0; i < 4; ++i) acc[ng][i] = 0.f;

#pragma unroll
    for (int kc = 0; kc < 8; ++kc) {
        const int k0 = kc * 16;
        unsigned a0 = *(const unsigned*)&wos[(w*16 + r)*OC_STRIDE + k0 + kq];
        unsigned a1 = *(const unsigned*)&wos[(w*16 + r + 8)*OC_STRIDE + k0 + kq];
        unsigned a2 = *(const unsigned*)&wos[(w*16 + r)*OC_STRIDE + k0 + kq + 8];
        unsigned a3 = *(const unsigned*)&wos[(w*16 + r + 8)*OC_STRIDE + k0 + kq + 8];
#pragma unroll
        for (int ng = 0; ng < 4; ++ng) {
            unsigned b0 = *(const unsigned*)&ats[(ng*8 + r)*OC_STRIDE + k0 + kq];
            unsigned b1 = *(const unsigned*)&ats[(ng*8 + r)*OC_STRIDE + k0 + kq + 8];
            mma_bf16(acc[ng][0], acc[ng][1], acc[ng][2], acc[ng][3],
                     a0, a1, a2, a3, b0, b1);
        }
    }

#pragma unroll
    for (int ng = 0; ng < 4; ++ng) {
        const int col = n0 + ng*8 + kq;
        size_t i0 = (size_t)(b*CC + w*16 + r)*NTOK + col;
        float2 x0 = *(const float2*)(x + i0);
        *(float2*)(out + i0) = make_float2(x0.x + acc[ng][0], x0.y + acc[ng][1]);
        size_t i1 = (size_t)(b*CC + w*16 + r + 8)*NTOK + col;
        float2 x1 = *(const float2*)(x + i1);
        *(float2*)(out + i1) = make_float2(x1.x + acc[ng][2], x1.y + acc[ng][3]);
    }
}

// =================================================================
extern "C" void kernel_launch(void* const* d_in, const int* in_sizes, int n_in,
                              void* d_out, int out_size)
{
    const float* x    = (const float*)d_in[0];
    const float* wq   = (const float*)d_in[1];
    const float* wk   = (const float*)d_in[2];
    const float* wv   = (const float*)d_in[3];
    const float* dwq  = (const float*)d_in[4];
    const float* dwk  = (const float*)d_in[5];
    const float* dwv  = (const float*)d_in[6];
    const float* wo   = (const float*)d_in[7];
    const float* temp = (const float*)d_in[8];
    float* out = (float*)d_out;

    cudaFuncSetAttribute(qkv_kernel, cudaFuncAttributeMaxDynamicSharedMemorySize, QKV_SMEM_BYTES);
    cudaFuncSetAttribute(attn_kernel, cudaFuncAttributeMaxDynamicSharedMemorySize, ATTN_SMEM_BYTES);
    cudaFuncSetAttribute(outconv_kernel, cudaFuncAttributeMaxDynamicSharedMemorySize, OC_SMEM_BYTES);

    qkv_kernel<<<BB*64, 768, QKV_SMEM_BYTES>>>(x, wq, wk, wv, dwq, dwk, dwv);
    attn_kernel<<<dim3(NTOK/16, BB*NHEADS), 512, ATTN_SMEM_BYTES>>>(temp);
    outconv_kernel<<<dim3(NTOK/32, BB), 256, OC_SMEM_BYTES>>>(x, wo, out);
}